// round 2
// baseline (speedup 1.0000x reference)
#include <cuda_runtime.h>
#include <math.h>

// SLAYFeatures: out[b, r, h, p, m] = poly[b,h,p] * prf[b,r,h,m]
//   poly[b,h,p] = (xn[b,h,:] . anchors[p,:])^2 / sqrt(P)
//   prf[b,r,h,m] = sqrt(w_r) * exp(clip(proj*sqrt(2 s_r) - s_r, +-20)) / sqrt(M)
//   proj = xn[b,h,:] . omega[r,h,:,m]
// B=8192, H=16, D=64, M=32, P=16, R=2.  Output [8192, 16384] f32 (512 MB) -> HBM-store-bound.

#define NB 8          // b-rows per block (amortizes omega L2 traffic 8x)
#define THREADS 256

__global__ __launch_bounds__(THREADS) void slay_kernel(
    const float* __restrict__ x,        // [8192,1024]
    const float* __restrict__ omega,    // [2,16,64,32]
    const float* __restrict__ anchors,  // [16,64]
    float* __restrict__ out,            // [8192,16384]
    float s0, float s1,                 // quad nodes / C
    float c0, float c1,                 // sqrt(2*s_r)
    float e0, float e1)                 // sqrt(w_r/C)/sqrt(M)
{
    __shared__ __align__(16) float xs[NB][1024];   // normalized x rows
    __shared__ __align__(16) float poly[NB][256];  // [b][h*16+p]

    const int t  = threadIdx.x;
    const int b0 = blockIdx.x * NB;

    // ---------- Phase 1: load x, per-head normalize ----------
    // float4 #t of each row covers floats [4t,4t+4) -> head = t/16; the 16
    // threads sharing a head are 16 consecutive lanes -> shfl_xor reduce.
    {
        float4 v[NB];
        float  ss[NB];
        const float4* x4 = (const float4*)x;
#pragma unroll
        for (int k = 0; k < NB; k++) {
            v[k] = x4[(size_t)(b0 + k) * 256 + t];
            ss[k] = v[k].x*v[k].x + v[k].y*v[k].y + v[k].z*v[k].z + v[k].w*v[k].w;
        }
#pragma unroll
        for (int k = 0; k < NB; k++) {
#pragma unroll
            for (int off = 8; off; off >>= 1)
                ss[k] += __shfl_xor_sync(0xffffffffu, ss[k], off);
            float inv = 1.0f / (sqrtf(fmaxf(ss[k], 1e-12f)) + 1e-4f);
            float4 w = v[k];
            w.x *= inv; w.y *= inv; w.z *= inv; w.w *= inv;
            ((float4*)xs[k])[t] = w;
        }
    }
    __syncthreads();

    // ---------- Phase 2: poly features. thread = (h, p) ----------
    {
        const int h = t >> 4, p = t & 15;
        float acc[NB];
#pragma unroll
        for (int k = 0; k < NB; k++) acc[k] = 0.0f;
        const float4* an = (const float4*)(anchors + p * 64);
#pragma unroll 4
        for (int d4 = 0; d4 < 16; d4++) {
            float4 a = an[d4];
#pragma unroll
            for (int k = 0; k < NB; k++) {
                float4 xv = ((const float4*)xs[k])[h * 16 + d4];
                acc[k] += xv.x*a.x + xv.y*a.y + xv.z*a.z + xv.w*a.w;
            }
        }
#pragma unroll
        for (int k = 0; k < NB; k++)
            poly[k][t] = acc[k] * acc[k] * 0.25f;   // /sqrt(P=16)
    }
    __syncthreads();

    // ---------- Phase 3: PRF features + fused outer-product store ----------
    // thread = (r, h, m4): 4 consecutive m per thread (float4 omega loads,
    // m-contiguous -> coalesced), 8 b-rows in registers.
    {
        const int r  = t >> 7;
        const int h  = (t >> 3) & 15;
        const int m4 = t & 7;

        float4 acc[NB];
#pragma unroll
        for (int k = 0; k < NB; k++) acc[k] = make_float4(0.f, 0.f, 0.f, 0.f);

        const float4* og = (const float4*)omega + (size_t)((r * 16 + h) * 64) * 8 + m4;
#pragma unroll 4
        for (int d4 = 0; d4 < 16; d4++) {
            float4 o0 = og[(4 * d4 + 0) * 8];
            float4 o1 = og[(4 * d4 + 1) * 8];
            float4 o2 = og[(4 * d4 + 2) * 8];
            float4 o3 = og[(4 * d4 + 3) * 8];
#pragma unroll
            for (int k = 0; k < NB; k++) {
                float4 xv = ((const float4*)xs[k])[h * 16 + d4];
                acc[k].x += xv.x*o0.x; acc[k].y += xv.x*o0.y; acc[k].z += xv.x*o0.z; acc[k].w += xv.x*o0.w;
                acc[k].x += xv.y*o1.x; acc[k].y += xv.y*o1.y; acc[k].z += xv.y*o1.z; acc[k].w += xv.y*o1.w;
                acc[k].x += xv.z*o2.x; acc[k].y += xv.z*o2.y; acc[k].z += xv.z*o2.z; acc[k].w += xv.z*o2.w;
                acc[k].x += xv.w*o3.x; acc[k].y += xv.w*o3.y; acc[k].z += xv.w*o3.z; acc[k].w += xv.w*o3.w;
            }
        }

        const float sr = r ? s1 : s0;
        const float cr = r ? c1 : c0;
        const float er = r ? e1 : e0;

#pragma unroll
        for (int k = 0; k < NB; k++) {
            float4 a = acc[k];
            float4 pr;
            pr.x = er * expf(fminf(fmaxf(a.x * cr - sr, -20.f), 20.f));
            pr.y = er * expf(fminf(fmaxf(a.y * cr - sr, -20.f), 20.f));
            pr.z = er * expf(fminf(fmaxf(a.z * cr - sr, -20.f), 20.f));
            pr.w = er * expf(fminf(fmaxf(a.w * cr - sr, -20.f), 20.f));

            float* ob = out + (size_t)(b0 + k) * 16384 + r * 8192 + h * 512 + m4 * 4;
            const float* pl = &poly[k][h * 16];
#pragma unroll
            for (int p = 0; p < 16; p++) {
                float pf = pl[p];
                float4 o;
                o.x = pf * pr.x; o.y = pf * pr.y; o.z = pf * pr.z; o.w = pf * pr.w;
                __stcs((float4*)(ob + p * 32), o);   // streaming store: write-once output
            }
        }
    }
}

extern "C" void kernel_launch(void* const* d_in, const int* in_sizes, int n_in,
                              void* d_out, int out_size) {
    const float* x       = (const float*)d_in[0];
    const float* omega   = (const float*)d_in[1];
    const float* anchors = (const float*)d_in[2];
    float* out = (float*)d_out;

    // Gauss-Laguerre (n=2) nodes/weights, scaled by 1/C, in double then f32.
    const double C   = 2.0 + 1e-6;
    const double rt2 = 1.4142135623730951;
    const double n0d = 2.0 - rt2, n1d = 2.0 + rt2;
    const double w0d = (2.0 + rt2) / 4.0, w1d = (2.0 - rt2) / 4.0;

    float s0 = (float)(n0d / C);
    float s1 = (float)(n1d / C);
    float c0 = sqrtf(2.0f * s0);
    float c1 = sqrtf(2.0f * s1);
    float invSqrtM = 1.0f / sqrtf(32.0f);
    float e0 = sqrtf((float)(w0d / C)) * invSqrtM;
    float e1 = sqrtf((float)(w1d / C)) * invSqrtM;

    dim3 grid(8192 / NB);
    dim3 block(THREADS);
    slay_kernel<<<grid, block>>>(x, omega, anchors, out, s0, s1, c0, c1, e0, e1);
    (void)in_sizes; (void)n_in; (void)out_size;
}